// round 12
// baseline (speedup 1.0000x reference)
#include <cuda_runtime.h>
#include <cuda_fp16.h>
#include <math.h>
#include <stdint.h>

// ---------------------------------------------------------------------------
// ENAS controller sampler. H=2048, NB=8, NC=8, TEMP=5, TANH_C=2.5, OP_RED=2.5
// R11: single persistent megakernel (444 blocks = 148 SMs x 3, guaranteed
// co-resident at >=4 blocks/SM by __launch_bounds__(256,4)) with software
// grid barriers. Each block owns a fixed w_hh slice -> L1-resident across all
// 84 steps (L1 only flushes per launch). w_ih/w_a1/w_a2 read via __ldcg to
// keep them out of L1. Idle blocks pre-touch w_hh during sample phases.
// fp16 weights (converted once), fp32 state/accum/sampling (as R8, passed).
// ---------------------------------------------------------------------------

#define H 2048
#define G4 8192   // 4*H
#define NBLK 444  // 148 SMs x 3 blocks

// scratch layout (floats)
#define OFF_H0   0
#define OFF_H1   (OFF_H0 + H)
#define OFF_C    (OFF_H1 + H)
#define OFF_HW2  (OFF_C + H)
#define OFF_AW1  (OFF_HW2 + H)            // 10 x 2048
#define OFF_AXP  (OFF_AW1 + 10*H)         // 10 x 8192 anchor x-projections
#define OFF_EXP  (OFF_AXP + 10*G4)        // 9 x 8192 encoder x-projections
#define OFF_BSUM (OFF_EXP + 9*G4)         // 8192 combined biases
#define SCR_TOTAL (OFF_BSUM + G4)

__device__ __align__(16) float    g_scratch[SCR_TOTAL];
__device__ int       g_sel[64];
__device__ unsigned  g_key[2];
__device__ float     g_acc[2];   // [0]=log_prob, [1]=entropy

// grid barrier state
__device__ unsigned           g_bar_ctr;
__device__ volatile unsigned  g_bar_gen;

// fp16 weight copies (static device arrays; ~81MB total)
__device__ __align__(16) __half g_whh_h[4 * H * H];
__device__ __align__(16) __half g_wih_h[4 * H * H];
__device__ __align__(16) __half g_wa1_h[H * H];
__device__ __align__(16) __half g_wa2_h[H * H];
__device__ __align__(16) __half g_wsoft_h[8 * H];

// ------------------------- grid barrier ------------------------------------
__device__ __forceinline__ void gbar()
{
    __syncthreads();
    if (threadIdx.x == 0) {
        __threadfence();
        unsigned gen = g_bar_gen;
        __threadfence();
        if (atomicAdd(&g_bar_ctr, 1u) == NBLK - 1) {
            g_bar_ctr = 0;
            __threadfence();
            g_bar_gen = gen + 1;
        } else {
            while (g_bar_gen == gen) __nanosleep(64);
        }
        __threadfence();
    }
    __syncthreads();
}

// ------------------------- Threefry-2x32 (20 rounds) -----------------------
__device__ __forceinline__ void tf2x32(unsigned k0, unsigned k1,
                                       unsigned x0, unsigned x1,
                                       unsigned &y0, unsigned &y1)
{
    const unsigned ks0 = k0, ks1 = k1, ks2 = k0 ^ k1 ^ 0x1BD11BDAu;
    x0 += ks0; x1 += ks1;
    const unsigned R[8] = {13u,15u,26u,6u,17u,29u,16u,24u};
    unsigned ks[3] = {ks0, ks1, ks2};
    #pragma unroll
    for (int i = 0; i < 5; i++) {
        #pragma unroll
        for (int j = 0; j < 4; j++) {
            unsigned r = R[(i & 1) * 4 + j];
            x0 += x1;
            x1 = (x1 << r) | (x1 >> (32u - r));
            x1 ^= x0;
        }
        x0 += ks[(i + 1) % 3];
        x1 += ks[(i + 2) % 3] + (unsigned)(i + 1);
    }
    y0 = x0; y1 = x1;
}

// partitionable-mode sampling: split + gumbel-argmax + log_softmax accounting
__device__ void do_sample(const float* l, int n, int* sel_slot, float* arc_out)
{
    unsigned k0 = g_key[0], k1 = g_key[1];
    unsigned nk0, nk1, s0, s1;
    tf2x32(k0, k1, 0u, 0u, nk0, nk1);   // new carry key
    tf2x32(k0, k1, 0u, 1u, s0, s1);     // subkey for this draw
    g_key[0] = nk0; g_key[1] = nk1;

    int best = 0; float bz = -3.4e38f;
    for (int a = 0; a < n; a++) {
        unsigned b1, b2;
        tf2x32(s0, s1, 0u, (unsigned)a, b1, b2);
        unsigned bits = b1 ^ b2;
        float f = __uint_as_float((bits >> 9) | 0x3F800000u) - 1.0f;
        float u = (f == 0.0f) ? 1.17549435e-38f : f;
        float g = -logf(-logf(u));
        float z = l[a] + g;
        if (z > bz) { bz = z; best = a; }
    }
    float mx = l[0];
    for (int a = 1; a < n; a++) mx = fmaxf(mx, l[a]);
    float se = 0.0f;
    for (int a = 0; a < n; a++) se += expf(l[a] - mx);
    float lse = logf(se);
    g_acc[0] += -((l[best] - mx) - lse);
    float ent = 0.0f;
    for (int a = 0; a < n; a++) {
        float ls = (l[a] - mx) - lse;
        ent -= ls * expf(ls);
    }
    g_acc[1] += ent;
    *sel_slot = best;
    *arc_out = (float)best;
}

// ------------------------------ small kernels ------------------------------
__global__ void init_kernel(const float* __restrict__ b_ih,
                            const float* __restrict__ b_hh)
{
    int i = blockIdx.x * blockDim.x + threadIdx.x;  // 16384 threads
    float* scr = g_scratch;
    if (i < H)      { scr[OFF_H0 + i] = 0.0f; scr[OFF_C + i] = 0.0f; }
    if (i < 2 * G4) scr[OFF_AXP + i] = 0.0f;
    if (i < G4)     scr[OFF_BSUM + i] = b_ih[i] + b_hh[i];
    if (i == 0) {
        g_key[0] = 0u; g_key[1] = 42u;
        g_acc[0] = 0.0f; g_acc[1] = 0.0f;
        g_bar_ctr = 0u;
    }
}

__device__ __forceinline__ void conv_seg(const float* __restrict__ s,
                                         __half* __restrict__ d,
                                         size_t n4, size_t tid, size_t stride)
{
    const float4* s4 = (const float4*)s;
    uint2* d4 = (uint2*)d;
    for (size_t i = tid; i < n4; i += stride) {
        float4 v = s4[i];
        __half2 a = __floats2half2_rn(v.x, v.y);
        __half2 b = __floats2half2_rn(v.z, v.w);
        d4[i] = make_uint2(*(unsigned*)&a, *(unsigned*)&b);
    }
}

__global__ void convert_kernel(const float* __restrict__ whh,
                               const float* __restrict__ wih,
                               const float* __restrict__ wa1,
                               const float* __restrict__ wa2,
                               const float* __restrict__ wsoft)
{
    size_t tid = (size_t)blockIdx.x * blockDim.x + threadIdx.x;
    size_t stride = (size_t)gridDim.x * blockDim.x;
    conv_seg(whh,   g_whh_h,   (size_t)4 * H * H / 4, tid, stride);
    conv_seg(wih,   g_wih_h,   (size_t)4 * H * H / 4, tid, stride);
    conv_seg(wa1,   g_wa1_h,   (size_t)H * H / 4,     tid, stride);
    conv_seg(wa2,   g_wa2_h,   (size_t)H * H / 4,     tid, stride);
    conv_seg(wsoft, g_wsoft_h, (size_t)8 * H / 4,     tid, stride);
}

// warp dot: 8 front-batched LDG.128 of packed half2 vs shared fp32 h.
// CG=true bypasses L1 (evict-normal L2) to protect the w_hh L1 residency.
template<bool CG>
__device__ __forceinline__ float wdot(const __half* __restrict__ wrow,
                                      const float4* __restrict__ sh4,
                                      int lane)
{
    const uint4* w4 = (const uint4*)wrow;
    uint4 wr[8];
    #pragma unroll
    for (int i = 0; i < 8; i++)
        wr[i] = CG ? __ldcg(w4 + lane + i * 32) : w4[lane + i * 32];
    float s = 0.0f;
    #pragma unroll
    for (int i = 0; i < 8; i++) {
        int idx = lane + i * 32;
        float4 ha = sh4[idx * 2];
        float4 hb = sh4[idx * 2 + 1];
        const __half2* hw = (const __half2*)&wr[i];
        float2 p0 = __half22float2(hw[0]);
        float2 p1 = __half22float2(hw[1]);
        float2 p2 = __half22float2(hw[2]);
        float2 p3 = __half22float2(hw[3]);
        s += p0.x * ha.x + p0.y * ha.y + p1.x * ha.z + p1.y * ha.w
           + p2.x * hb.x + p2.y * hb.y + p3.x * hb.z + p3.y * hb.w;
    }
    #pragma unroll
    for (int o = 16; o > 0; o >>= 1) s += __shfl_down_sync(0xffffffffu, s, o);
    return s;
}

// encoder_xproj[e][j] = sum_k enc[e,k] * w_ih[j,k]; warp-per-row, grid 1024
__global__ void __launch_bounds__(256)
encproj_kernel(const float* __restrict__ enc)
{
    int t = threadIdx.x;
    int w = t >> 5, lane = t & 31;
    int j = blockIdx.x * 8 + w;          // 0..8191
    float* expo = g_scratch + OFF_EXP;
    const uint4* w4 = (const uint4*)(g_wih_h + (size_t)j * H);
    uint4 wr[8];
    #pragma unroll
    for (int i = 0; i < 8; i++) wr[i] = w4[lane + i * 32];
    const float4* e4 = (const float4*)enc;
    #pragma unroll 1
    for (int e = 0; e < 9; e++) {
        float s = 0.0f;
        #pragma unroll
        for (int i = 0; i < 8; i++) {
            int idx = lane + i * 32;
            float4 ha = __ldg(&e4[e * 512 + idx * 2]);
            float4 hb = __ldg(&e4[e * 512 + idx * 2 + 1]);
            const __half2* hw = (const __half2*)&wr[i];
            float2 p0 = __half22float2(hw[0]);
            float2 p1 = __half22float2(hw[1]);
            float2 p2 = __half22float2(hw[2]);
            float2 p3 = __half22float2(hw[3]);
            s += p0.x * ha.x + p0.y * ha.y + p1.x * ha.z + p1.y * ha.w
               + p2.x * hb.x + p2.y * hb.y + p3.x * hb.z + p3.y * hb.w;
        }
        #pragma unroll
        for (int o = 16; o > 0; o >>= 1) s += __shfl_down_sync(0xffffffffu, s, o);
        if (lane == 0) expo[(size_t)e * G4 + j] = s;
    }
}

// ------------------------- megakernel phase helpers ------------------------
// Pre-touch this block's fixed w_hh slice into L1 (used during idle phases).
__device__ __forceinline__ void pretouch_whh(int b, int t)
{
    int c0 = (b * 2048) / NBLK, c1 = ((b + 1) * 2048) / NBLK;
    int nrows = (c1 - c0) * 4;
    int nlines = nrows * 32;    // 128B lines per 4KB row
    for (int i = t; i < nlines; i += 256) {
        int lr = i >> 5, li = i & 31;
        int cl = lr >> 2, g = lr & 3;
        const char* p = (const char*)(g_whh_h +
                         ((size_t)(g * 2048 + c0 + cl)) * 2048) + li * 128;
        unsigned tmp;
        asm volatile("ld.global.ca.b32 %0, [%1];" : "=r"(tmp) : "l"(p) : "memory");
    }
}

// One LSTM cell step over this block's cols + optional fused anchor proj.
__device__ void lstm_phase(int b, int t, int w, int lane,
                           const float* xp_base, int tcidx, int off,
                           const float* h_in, float* h_out, float* cvec,
                           const float* bsum,
                           int proj_mode,       // 0 none, 1 aw1 only, 2 both
                           float* aw1_slot, float* axp_slot,
                           float4* sh4, float* sred)
{
    const float4* h4 = (const float4*)h_in;
    sh4[t]       = h4[t];
    sh4[t + 256] = h4[t + 256];
    __syncthreads();
    int c0 = (b * 2048) / NBLK, c1 = ((b + 1) * 2048) / NBLK;
    int nrows = (c1 - c0) * 4;
    for (int lr = w; lr < nrows; lr += 8) {
        int cl = lr >> 2, g = lr & 3;
        float s = wdot<false>(g_whh_h + ((size_t)(g * 2048 + c0 + cl)) * 2048,
                              sh4, lane);
        if (lane == 0) sred[lr] = s;
    }
    __syncthreads();
    if (t < c1 - c0) {
        int j = c0 + t;
        int slot = (tcidx < 0) ? 0 : (g_sel[tcidx] + off);
        const float* xp = xp_base + (size_t)slot * G4;
        float gi = sred[t * 4 + 0] + xp[j]        + bsum[j];
        float gf = sred[t * 4 + 1] + xp[j + 2048] + bsum[j + 2048];
        float gg = sred[t * 4 + 2] + xp[j + 4096] + bsum[j + 4096];
        float go = sred[t * 4 + 3] + xp[j + 6144] + bsum[j + 6144];
        float si = 1.0f / (1.0f + expf(-gi));
        float sf = 1.0f / (1.0f + expf(-gf));
        float so = 1.0f / (1.0f + expf(-go));
        float cn = sf * cvec[j] + si * tanhf(gg);
        cvec[j] = cn;
        h_out[j] = so * tanhf(cn);
    }
    if (proj_mode) {
        int total = (proj_mode == 1) ? 2048 : 10240;
        for (int r = b * 8 + w; r < total; r += NBLK * 8) {
            float s;
            if (r < 2048) s = wdot<true>(g_wa1_h + (size_t)r * 2048, sh4, lane);
            else          s = wdot<true>(g_wih_h + (size_t)(r - 2048) * 2048,
                                         sh4, lane);
            if (lane == 0) {
                if (r < 2048) aw1_slot[r] = s;
                else          axp_slot[r - 2048] = s;
            }
        }
    }
}

// hw2 = w_a2 @ h (blocks 0..255; others pre-touch w_hh)
__device__ void attn_mv_phase(int b, int t, int w, int lane,
                              const float* h_in, float* hw2, float4* sh4)
{
    if (b < 256) {
        const float4* h4 = (const float4*)h_in;
        sh4[t]       = h4[t];
        sh4[t + 256] = h4[t + 256];
        __syncthreads();
        int r = b * 8 + w;
        float s = wdot<true>(g_wa2_h + (size_t)r * 2048, sh4, lane);
        if (lane == 0) hw2[r] = s;
    } else {
        pretouch_whh(b, t);
    }
}

__device__ void sample_idx_phase(int b, int t, int n, int tcslot, float* outp,
                                 const float* v_attn, const float* aw1,
                                 const float* hw2, float* sred)
{
    __shared__ float slog[10];
    if (b == 0) {
        for (int a = 0; a < n; a++) {
            float ss = 0.0f;
            for (int k = t; k < H; k += 256)
                ss += tanhf(aw1[(size_t)a * H + k] + hw2[k]) * v_attn[k];
            #pragma unroll
            for (int o = 16; o > 0; o >>= 1)
                ss += __shfl_down_sync(0xffffffffu, ss, o);
            if ((t & 31) == 0) sred[t >> 5] = ss;
            __syncthreads();
            if (t == 0) {
                float tot = 0.0f;
                for (int wp = 0; wp < 8; wp++) tot += sred[wp];
                slog[a] = tot;
            }
            __syncthreads();
        }
        if (t == 0) {
            float l[10];
            for (int a = 0; a < n; a++) l[a] = 2.5f * tanhf(slog[a] / 5.0f);
            do_sample(l, n, &g_sel[tcslot], outp);
        }
    } else {
        pretouch_whh(b, t);
    }
}

__device__ void sample_op_phase(int b, int t, int use_bias, int tcslot,
                                float* outp, const float* h,
                                const float* b_soft, const float* b_nl,
                                float* sred)
{
    __shared__ float slog2[8];
    if (b == 0) {
        for (int rr = 0; rr < 8; rr++) {
            float ss = 0.0f;
            for (int k = t; k < H; k += 256)
                ss += h[k] * __half2float(g_wsoft_h[(size_t)rr * H + k]);
            #pragma unroll
            for (int o = 16; o > 0; o >>= 1)
                ss += __shfl_down_sync(0xffffffffu, ss, o);
            if ((t & 31) == 0) sred[t >> 5] = ss;
            __syncthreads();
            if (t == 0) {
                float tot = 0.0f;
                for (int wp = 0; wp < 8; wp++) tot += sred[wp];
                slog2[rr] = tot;
            }
            __syncthreads();
        }
        if (t == 0) {
            float l[8];
            for (int rr = 0; rr < 8; rr++) {
                float v = tanhf((slog2[rr] + b_soft[rr]) / 5.0f); // *(2.5/2.5)=1
                if (use_bias) v += b_nl[rr];
                l[rr] = v;
            }
            do_sample(l, 8, &g_sel[tcslot], outp);
        }
    } else {
        pretouch_whh(b, t);
    }
}

// ------------------------------- megakernel --------------------------------
__global__ void __launch_bounds__(256, 4)
mega_kernel(const float* __restrict__ b_soft,
            const float* __restrict__ b_nl,
            const float* __restrict__ v_at,
            float* __restrict__ out)
{
    __shared__ float4 sh4[512];
    __shared__ float sred[32];
    int b = blockIdx.x, t = threadIdx.x;
    int w = t >> 5, lane = t & 31;

    float* scr  = g_scratch;
    float* hb0  = scr + OFF_H0;
    float* hb1  = scr + OFF_H1;
    float* cvec = scr + OFF_C;
    float* hw2  = scr + OFF_HW2;
    float* aw1  = scr + OFF_AW1;
    float* axp  = scr + OFF_AXP;
    float* expo = scr + OFF_EXP;
    float* bsum = scr + OFF_BSUM;

    int hp = 0, tc = 0;

    #define LSTM(XPB, TCI, OFFS, PM, PO1, PO2) do { \
        float* hi = hp ? hb1 : hb0; \
        float* ho = hp ? hb0 : hb1; \
        lstm_phase(b, t, w, lane, (XPB), (TCI), (OFFS), hi, ho, cvec, bsum, \
                   (PM), (PO1), (PO2), sh4, sred); \
        hp ^= 1; gbar(); \
    } while (0)

    for (int s = 0; s < 2; s++) {
        int ub = (s == 0) ? 1 : 0;
        // warmup w0: plain LSTM on encoder row 0
        LSTM(expo, -1, 0, 0, nullptr, nullptr);
        // warmup w1: LSTM + proj of w0's h into aw1 slot 0
        LSTM(expo, -1, 0, 1, aw1 + 0 * H, nullptr);

        for (int l = 0; l < 8; l++) {
            int n = l + 2;
            int base = s * 32 + l * 4;
            // idx0 (input = encoder row 0) + fused proj of prev h into slot l+1
            LSTM(expo, -1, 0, (l == 0) ? 1 : 2,
                 aw1 + (size_t)(l + 1) * H, axp + (size_t)(l + 1) * G4);
            {
                float* hcur = hp ? hb1 : hb0;
                attn_mv_phase(b, t, w, lane, hcur, hw2, sh4); gbar();
                sample_idx_phase(b, t, n, tc, out + base + 0, v_at, aw1, hw2,
                                 sred); gbar();
            }
            int t0 = tc++;
            // idx1 (input = anchors[idx0])
            LSTM(axp, t0, 0, 0, nullptr, nullptr);
            {
                float* hcur = hp ? hb1 : hb0;
                attn_mv_phase(b, t, w, lane, hcur, hw2, sh4); gbar();
                sample_idx_phase(b, t, n, tc, out + base + 2, v_at, aw1, hw2,
                                 sred); gbar();
            }
            int t1 = tc++;
            // op0 (input = anchors[idx1])
            LSTM(axp, t1, 0, 0, nullptr, nullptr);
            {
                float* hcur = hp ? hb1 : hb0;
                sample_op_phase(b, t, ub, tc, out + base + 1, hcur,
                                b_soft, b_nl, sred); gbar();
            }
            int t2 = tc++;
            // op1 (input = encoder[op0 + 1])
            LSTM(expo, t2, 1, 0, nullptr, nullptr);
            {
                float* hcur = hp ? hb1 : hb0;
                sample_op_phase(b, t, ub, tc, out + base + 3, hcur,
                                b_soft, b_nl, sred); gbar();
            }
            int t3 = tc++;
            // anchor step (input = encoder[op1 + 1]); proj fused into next
            // idx0 (or dropped for l==7: slot 9 is never read)
            LSTM(expo, t3, 1, 0, nullptr, nullptr);
        }
    }
    if (b == 0 && t == 0) {
        out[64] = g_acc[0];
        out[65] = g_acc[1];
    }
    #undef LSTM
}

// ------------------------------- launcher ----------------------------------
extern "C" void kernel_launch(void* const* d_in, const int* in_sizes, int n_in,
                              void* d_out, int out_size)
{
    const float* enc    = (const float*)d_in[0];
    const float* w_ih   = (const float*)d_in[1];
    const float* b_ih   = (const float*)d_in[2];
    const float* w_hh   = (const float*)d_in[3];
    const float* b_hh   = (const float*)d_in[4];
    const float* w_soft = (const float*)d_in[5];
    const float* b_soft = (const float*)d_in[6];
    const float* b_nl   = (const float*)d_in[7];
    const float* w_a1   = (const float*)d_in[8];
    const float* w_a2   = (const float*)d_in[9];
    const float* v_at   = (const float*)d_in[10];
    float* out = (float*)d_out;

    init_kernel<<<64, 256>>>(b_ih, b_hh);
    convert_kernel<<<2048, 256>>>(w_hh, w_ih, w_a1, w_a2, w_soft);
    encproj_kernel<<<1024, 256>>>(enc);
    mega_kernel<<<NBLK, 256>>>(b_soft, b_nl, v_at, out);
}